// round 6
// baseline (speedup 1.0000x reference)
#include <cuda_runtime.h>
#include <cuda_bf16.h>
#include <cstdint>

#define BB 8
#define HW 3072
#define KK 9216
#define SZ_PROB (8*18*3072)
#define SZ_BBOX (8*36*3072)
#define OUT_LCLS (SZ_PROB+SZ_BBOX)
#define OUT_LBOX (SZ_PROB+SZ_BBOX+1)
#define NCH 144
#define STGB 65536
#define SMEM_HMMA (3*STGB)

// ---------------- device scratch ----------------
__device__ float g_conv1[(size_t)BB*512*HW];
__device__ __align__(256) __nv_bfloat16 g_xhi[(size_t)BB*HW*1024];
__device__ __align__(256) __nv_bfloat16 g_xlo[(size_t)BB*HW*1024];
__device__ __align__(256) __nv_bfloat16 g_whi[(size_t)512*KK];
__device__ __align__(256) __nv_bfloat16 g_wlo[(size_t)512*KK];
__device__ float g_wh[512*56];
__device__ float g_cls[SZ_PROB];
__device__ float g_acc[3];

// ---------------- PTX helpers ----------------
__device__ __forceinline__ uint32_t smem_u32(const void* p) {
  uint32_t a;
  asm("{ .reg .u64 t; cvta.to.shared.u64 t, %1; cvt.u32.u64 %0, t; }" : "=r"(a) : "l"(p));
  return a;
}
__device__ __forceinline__ void cpa16(uint32_t dst, const void* src, int sz) {
  asm volatile("cp.async.cg.shared.global [%0], [%1], 16, %2;"
               :: "r"(dst), "l"(src), "r"(sz) : "memory");
}
#define CPA_COMMIT asm volatile("cp.async.commit_group;" ::: "memory")
#define CPA_WAIT1  asm volatile("cp.async.wait_group 1;" ::: "memory")
__device__ __forceinline__ void ldsm4(uint32_t* r, uint32_t a) {
  asm volatile("ldmatrix.sync.aligned.m8n8.x4.shared.b16 {%0,%1,%2,%3}, [%4];"
    : "=r"(r[0]), "=r"(r[1]), "=r"(r[2]), "=r"(r[3]) : "r"(a));
}
__device__ __forceinline__ void mma16816(float* c, const uint32_t* a, const uint32_t* b) {
  asm volatile("mma.sync.aligned.m16n8k16.row.col.f32.bf16.bf16.f32 "
    "{%0,%1,%2,%3}, {%4,%5,%6,%7}, {%8,%9}, {%0,%1,%2,%3};"
    : "+f"(c[0]), "+f"(c[1]), "+f"(c[2]), "+f"(c[3])
    : "r"(a[0]), "r"(a[1]), "r"(a[2]), "r"(a[3]), "r"(b[0]), "r"(b[1]));
}

// ---------------- misc ----------------
__device__ __forceinline__ float blockReduceSum(float v) {
  __shared__ float sh[32];
  __syncthreads();
  #pragma unroll
  for (int o = 16; o; o >>= 1) v += __shfl_down_sync(0xffffffffu, v, o);
  int lane = threadIdx.x & 31, wid = threadIdx.x >> 5;
  if (lane == 0) sh[wid] = v;
  __syncthreads();
  int nw = blockDim.x >> 5;
  v = (threadIdx.x < (unsigned)nw) ? sh[threadIdx.x] : 0.f;
  if (wid == 0) {
    #pragma unroll
    for (int o = 16; o; o >>= 1) v += __shfl_down_sync(0xffffffffu, v, o);
  }
  return v;
}

__global__ void k_prep0(const float* __restrict__ Wcls, const float* __restrict__ Wbb) {
  int i = blockIdx.x * 256 + threadIdx.x;
  if (i < 3) g_acc[i] = 0.f;
  if (i < 512 * 56) {
    int ic = i / 56, ch = i - ic * 56;
    float v = 0.f;
    if (ch < 18) v = Wcls[ch * 512 + ic];
    else if (ch < 54) v = Wbb[(ch - 18) * 512 + ic];
    g_wh[i] = v;
  }
}

__global__ void k_split_w(const float* __restrict__ Wc) {
  int i = blockIdx.x * 256 + threadIdx.x;
  if (i >= 512 * KK) return;
  int oc = i / KK, k = i - oc * KK;
  int tap = k >> 10, ic = k & 1023;
  float v = Wc[(size_t)oc * KK + ic * 9 + tap];
  __nv_bfloat16 hi = __float2bfloat16(v);
  __nv_bfloat16 lo = __float2bfloat16(v - __bfloat162float(hi));
  g_whi[i] = hi; g_wlo[i] = lo;
}

__global__ void k_nhwc(const float* __restrict__ x) {
  __shared__ float t[32][33];
  int s0 = blockIdx.x * 32, ic0 = blockIdx.y * 32, b = blockIdx.z;
  int tx = threadIdx.x, ty = threadIdx.y;
  #pragma unroll
  for (int i = 0; i < 4; i++)
    t[ty + i * 8][tx] = x[((size_t)b * 1024 + ic0 + ty + i * 8) * HW + s0 + tx];
  __syncthreads();
  #pragma unroll
  for (int i = 0; i < 4; i++) {
    float v = t[tx][ty + i * 8];
    __nv_bfloat16 hi = __float2bfloat16(v);
    __nv_bfloat16 lo = __float2bfloat16(v - __bfloat162float(hi));
    size_t o = ((size_t)b * HW + s0 + ty + i * 8) * 1024 + ic0 + tx;
    g_xhi[o] = hi; g_xlo[o] = lo;
  }
}

// ---------------- HMMA implicit-GEMM: 128x128 tile, 512 thr (16 warps, 32x32/warp) ----------------
__global__ void __launch_bounds__(512, 1) k_hmma(const float* __restrict__ bias) {
  extern __shared__ __align__(1024) char smc[];
  const uint32_t smb = smem_u32(smc);
  const int tid  = threadIdx.x;
  const int lane = tid & 31, wid = tid >> 5;
  const int m0 = blockIdx.x * 128;
  const int n0 = blockIdx.y * 128;
  const int b  = m0 / HW;
  const int s0 = m0 - b * HW;
  const int wm = wid & 3, wn = wid >> 2;   // 4x4 warp grid, 32x32 per warp

  float acc[2][4][4];
  #pragma unroll
  for (int i = 0; i < 2; i++)
    #pragma unroll
    for (int j = 0; j < 4; j++)
      #pragma unroll
      for (int k = 0; k < 4; k++) acc[i][j][k] = 0.f;

  // loader decomposition: 16 chunk-cols x 32 row-groups x 4 rows (A and B)
  const int cA  = tid & 15;             // 16B chunk within 256B row
  const int hl  = cA >> 3;              // 0=hi, 1=lo
  const int k16 = cA & 7;
  const int rT  = tid >> 4;             // 0..31
  const __nv_bfloat16* xsrc = hl ? g_xlo : g_xhi;
  const __nv_bfloat16* wsrc = hl ? g_wlo : g_whi;

  int hh[4], ww4[4];
  #pragma unroll
  for (int t = 0; t < 4; t++) {
    int sp = s0 + rT + 32 * t;
    hh[t] = sp / 48; ww4[t] = sp - hh[t] * 48;
  }

  auto issue_chunk = [&](int c) {
    const int st = c % 3;
    const uint32_t stb = smb + st * STGB;
    const int tap = c >> 4;
    const int icb = (c & 15) << 6;
    const int dh = tap / 3 - 1, dw = tap % 3 - 1;
    const int koff = icb + k16 * 8;
    #pragma unroll
    for (int t = 0; t < 4; t++) {
      int row = rT + 32 * t;
      int gh = hh[t] + dh, gw = ww4[t] + dw;
      bool ok = ((unsigned)gh < 64u) & ((unsigned)gw < 48u);
      int spg = ok ? (gh * 48 + gw) : 0;
      const void* src = xsrc + (((size_t)b * HW + spg) << 10) + koff;
      cpa16(stb + row * 256 + ((cA ^ (row & 7)) << 4), src, ok ? 16 : 0);
    }
    #pragma unroll
    for (int t = 0; t < 4; t++) {
      int row = rT + 32 * t;
      const void* src = wsrc + (size_t)(n0 + row) * KK + (c << 6) + k16 * 8;
      cpa16(stb + 32768 + row * 256 + ((cA ^ (row & 7)) << 4), src, 16);
    }
    CPA_COMMIT;
  };

  issue_chunk(0);
  issue_chunk(1);

  // fragment addressing precompute
  const int rowA  = wm * 32 + (lane & 15);
  const int khalf = lane >> 4;
  const int rowB  = wn * 32 + (lane >> 4) * 8 + (lane & 7);  // ntl = lane>>4
  const int khB   = (lane >> 3) & 1;

  #pragma unroll 1
  for (int c = 0; c < NCH; ++c) {
    CPA_WAIT1;
    __syncthreads();
    if (c + 2 < NCH) issue_chunk(c + 2);
    else CPA_COMMIT;

    const uint32_t aB = smb + (c % 3) * STGB;
    const uint32_t bB = aB + 32768;
    #pragma unroll
    for (int s = 0; s < 4; s++) {
      uint32_t ah[2][4], al[2][4], bq[2][4], bql[2][4];
      {
        #pragma unroll
        for (int mt = 0; mt < 2; mt++) {
          int r = rowA + mt * 16;
          int cH = 2 * s + khalf;
          int cL = 8 + cH;
          ldsm4(ah[mt], aB + r * 256 + ((cH ^ (r & 7)) << 4));
          ldsm4(al[mt], aB + r * 256 + ((cL ^ (r & 7)) << 4));
        }
        #pragma unroll
        for (int ntp = 0; ntp < 2; ntp++) {
          int r = rowB + ntp * 16;
          int cH = 2 * s + khB;
          int cL = 8 + cH;
          ldsm4(bq[ntp],  bB + r * 256 + ((cH ^ (r & 7)) << 4));
          ldsm4(bql[ntp], bB + r * 256 + ((cL ^ (r & 7)) << 4));
        }
      }
      #pragma unroll
      for (int mt = 0; mt < 2; mt++)
        #pragma unroll
        for (int nt = 0; nt < 4; nt++) {
          const uint32_t* bhF = &bq[nt >> 1][(nt & 1) * 2];
          const uint32_t* blF = &bql[nt >> 1][(nt & 1) * 2];
          mma16816(acc[mt][nt], ah[mt], bhF);
          mma16816(acc[mt][nt], al[mt], bhF);
          mma16816(acc[mt][nt], ah[mt], blF);
        }
    }
  }
  __syncthreads();

  // -------- epilogue: smem transpose -> coalesced stores, bias+relu --------
  float* so = (float*)smc;   // [128 oc][128 m] = 64KB
  const int g = lane >> 2, tg = lane & 3;
  #pragma unroll
  for (int mt = 0; mt < 2; mt++)
    #pragma unroll
    for (int nt = 0; nt < 4; nt++) {
      int r0 = wm * 32 + mt * 16 + g;
      int c0 = wn * 32 + nt * 8 + tg * 2;
      so[c0 * 128 + r0]           = acc[mt][nt][0];
      so[(c0 + 1) * 128 + r0]     = acc[mt][nt][1];
      so[c0 * 128 + r0 + 8]       = acc[mt][nt][2];
      so[(c0 + 1) * 128 + r0 + 8] = acc[mt][nt][3];
    }
  __syncthreads();
  #pragma unroll 1
  for (int i = tid; i < 128 * 32; i += 512) {
    int oc = i >> 5, mq = i & 31;
    float4 v = ((const float4*)(so + oc * 128))[mq];
    float bz = bias[n0 + oc];
    v.x = fmaxf(v.x + bz, 0.f); v.y = fmaxf(v.y + bz, 0.f);
    v.z = fmaxf(v.z + bz, 0.f); v.w = fmaxf(v.w + bz, 0.f);
    *(float4*)(g_conv1 + ((size_t)(b * 512 + n0 + oc)) * HW + s0 + mq * 4) = v;
  }
}

// ---------------- heads / losses ----------------
__global__ void __launch_bounds__(256) k_heads(const float* __restrict__ bcls,
                                               const float* __restrict__ bbb,
                                               float* __restrict__ out) {
  __shared__ __align__(16) float sx[64 * 128];
  __shared__ __align__(16) float sw[64 * 56];
  const int t = blockIdx.x;
  const int b = t / 24;
  const int sp0 = (t % 24) * 128;
  const int tid = threadIdx.x;
  const int sp = tid & 127;
  const int half = tid >> 7;

  float accv[28];
  #pragma unroll
  for (int j = 0; j < 28; j++) accv[j] = 0.f;

  #pragma unroll 1
  for (int ic0 = 0; ic0 < 512; ic0 += 64) {
    __syncthreads();
    {
      float4* dst = (float4*)sx;
      #pragma unroll 1
      for (int i = tid; i < 2048; i += 256) {
        int ic = i >> 5, c = i & 31;
        dst[i] = *(const float4*)(g_conv1 + (size_t)(b * 512 + ic0 + ic) * HW + sp0 + c * 4);
      }
      float4* dw = (float4*)sw;
      const float4* srw = (const float4*)(g_wh + ic0 * 56);
      #pragma unroll 1
      for (int i = tid; i < 896; i += 256) dw[i] = srw[i];
    }
    __syncthreads();
    #pragma unroll 1
    for (int ic = 0; ic < 64; ic++) {
      float xv = sx[ic * 128 + sp];
      const float* wr = sw + ic * 56 + half * 28;
      #pragma unroll
      for (int j = 0; j < 28; j++) accv[j] = fmaf(xv, wr[j], accv[j]);
    }
  }
  const int chb = half * 28;
  #pragma unroll
  for (int j = 0; j < 28; j++) {
    int ch = chb + j;
    if (ch < 54) {
      float bz = (ch < 18) ? bcls[ch] : bbb[ch - 18];
      float v = accv[j] + bz;
      if (ch < 18) g_cls[(size_t)(b * 18 + ch) * HW + sp0 + sp] = v;
      else         out[SZ_PROB + (size_t)(b * 36 + (ch - 18)) * HW + sp0 + sp] = v;
    }
  }
}

__global__ void __launch_bounds__(256) k_cls(const int* __restrict__ label,
                                             float* __restrict__ out) {
  int idx = blockIdx.x * 256 + threadIdx.x;
  float nll = 0.f, cnt = 0.f;
  if (idx < BB * 9 * HW) {
    int b = idx / (9 * HW);
    int rem = idx - b * (9 * HW);
    int a = rem / HW;
    int s = rem - a * HW;
    float l0 = g_cls[(size_t)(b * 18 + a) * HW + s];
    float l1 = g_cls[(size_t)(b * 18 + a + 9) * HW + s];
    float mx = fmaxf(l0, l1);
    float e0 = expf(l0 - mx), e1 = expf(l1 - mx);
    float sum = e0 + e1, inv = 1.f / sum;
    out[(size_t)(b * 18 + a) * HW + s] = e0 * inv;
    out[(size_t)(b * 18 + a + 9) * HW + s] = e1 * inv;
    int lb = label[idx];
    if (lb >= 0) {
      float chosen = lb ? l1 : l0;
      nll = -(chosen - mx - logf(sum));
      cnt = 1.f;
    }
  }
  float s1 = blockReduceSum(nll);
  if (threadIdx.x == 0) atomicAdd(&g_acc[0], s1);
  float s2 = blockReduceSum(cnt);
  if (threadIdx.x == 0) atomicAdd(&g_acc[1], s2);
}

__global__ void __launch_bounds__(256) k_box(const float* __restrict__ tgt,
                                             const float* __restrict__ iw,
                                             const float* __restrict__ ow,
                                             const float* __restrict__ bbox) {
  int i = blockIdx.x * 256 + threadIdx.x;
  float v = 0.f;
  if (i < SZ_BBOX) {
    float d = iw[i] * (bbox[i] - tgt[i]);
    float ad = fabsf(d);
    float l = (ad < (1.f / 9.f)) ? d * d * 4.5f : (ad - (1.f / 18.f));
    v = ow[i] * l;
  }
  float s = blockReduceSum(v);
  if (threadIdx.x == 0) atomicAdd(&g_acc[2], s);
}

__global__ void k_fin(float* out) {
  out[OUT_LCLS] = g_acc[0] / fmaxf(g_acc[1], 1.f);
  out[OUT_LBOX] = g_acc[2] * 0.125f;
}

// ---------------- host ----------------
extern "C" void kernel_launch(void* const* d_in, const int* in_sizes, int n_in,
                              void* d_out, int out_size) {
  const float* base_feat = (const float*)d_in[0];
  const float* W_conv = (const float*)d_in[1];
  const float* b_conv = (const float*)d_in[2];
  const float* W_cls  = (const float*)d_in[3];
  const float* b_cls  = (const float*)d_in[4];
  const float* W_bbox = (const float*)d_in[5];
  const float* b_bbox = (const float*)d_in[6];
  const int* rpn_label = (const int*)d_in[7];
  const float* tgt = (const float*)d_in[8];
  const float* iw  = (const float*)d_in[9];
  const float* ow  = (const float*)d_in[10];
  float* out = (float*)d_out;

  static int init = 0;
  if (!init) {
    cudaFuncSetAttribute(k_hmma, cudaFuncAttributeMaxDynamicSharedMemorySize, SMEM_HMMA);
    init = 1;
  }

  k_prep0<<<(512 * 56 + 255) / 256, 256>>>(W_cls, W_bbox);
  k_split_w<<<(512 * KK + 255) / 256, 256>>>(W_conv);
  k_nhwc<<<dim3(96, 32, 8), dim3(32, 8)>>>(base_feat);
  k_hmma<<<dim3(192, 4), 512, SMEM_HMMA>>>(b_conv);
  k_heads<<<192, 256>>>(b_cls, b_bbox, out);
  k_cls<<<(BB * 9 * HW + 255) / 256, 256>>>(rpn_label, out);
  k_box<<<(SZ_BBOX + 255) / 256, 256>>>(tgt, iw, ow, out + SZ_PROB);
  k_fin<<<1, 1>>>(out);
}

// round 7
// speedup vs baseline: 1.1031x; 1.1031x over previous
#include <cuda_runtime.h>
#include <cuda_bf16.h>
#include <cstdint>

#define BB 8
#define HW 3072
#define KK 9216
#define SZ_PROB (8*18*3072)
#define SZ_BBOX (8*36*3072)
#define OUT_LCLS (SZ_PROB+SZ_BBOX)
#define OUT_LBOX (SZ_PROB+SZ_BBOX+1)
#define NCH 144
#define ASZ 24576              // A tile bytes: 96 rows * 256B
#define STGB 57344             // ASZ + 128*256
#define SMEM_HMMA (3*STGB)     // 172032

// ---------------- device scratch ----------------
__device__ float g_conv1[(size_t)BB*512*HW];
__device__ __align__(256) __nv_bfloat16 g_xhi[(size_t)BB*HW*1024];
__device__ __align__(256) __nv_bfloat16 g_xlo[(size_t)BB*HW*1024];
__device__ __align__(256) __nv_bfloat16 g_whi[(size_t)512*KK];
__device__ __align__(256) __nv_bfloat16 g_wlo[(size_t)512*KK];
__device__ float g_wh[512*56];
__device__ float g_cls[SZ_PROB];
__device__ float g_acc[3];

// ---------------- PTX helpers ----------------
__device__ __forceinline__ uint32_t smem_u32(const void* p) {
  uint32_t a;
  asm("{ .reg .u64 t; cvta.to.shared.u64 t, %1; cvt.u32.u64 %0, t; }" : "=r"(a) : "l"(p));
  return a;
}
__device__ __forceinline__ void cpa16(uint32_t dst, const void* src, int sz) {
  asm volatile("cp.async.cg.shared.global [%0], [%1], 16, %2;"
               :: "r"(dst), "l"(src), "r"(sz) : "memory");
}
#define CPA_COMMIT asm volatile("cp.async.commit_group;" ::: "memory")
#define CPA_WAIT1  asm volatile("cp.async.wait_group 1;" ::: "memory")
__device__ __forceinline__ void ldsm4(uint32_t* r, uint32_t a) {
  asm volatile("ldmatrix.sync.aligned.m8n8.x4.shared.b16 {%0,%1,%2,%3}, [%4];"
    : "=r"(r[0]), "=r"(r[1]), "=r"(r[2]), "=r"(r[3]) : "r"(a));
}
__device__ __forceinline__ void mma16816(float* c, const uint32_t* a, const uint32_t* b) {
  asm volatile("mma.sync.aligned.m16n8k16.row.col.f32.bf16.bf16.f32 "
    "{%0,%1,%2,%3}, {%4,%5,%6,%7}, {%8,%9}, {%0,%1,%2,%3};"
    : "+f"(c[0]), "+f"(c[1]), "+f"(c[2]), "+f"(c[3])
    : "r"(a[0]), "r"(a[1]), "r"(a[2]), "r"(a[3]), "r"(b[0]), "r"(b[1]));
}

// ---------------- misc ----------------
__device__ __forceinline__ float blockReduceSum(float v) {
  __shared__ float sh[32];
  __syncthreads();
  #pragma unroll
  for (int o = 16; o; o >>= 1) v += __shfl_down_sync(0xffffffffu, v, o);
  int lane = threadIdx.x & 31, wid = threadIdx.x >> 5;
  if (lane == 0) sh[wid] = v;
  __syncthreads();
  int nw = blockDim.x >> 5;
  v = (threadIdx.x < (unsigned)nw) ? sh[threadIdx.x] : 0.f;
  if (wid == 0) {
    #pragma unroll
    for (int o = 16; o; o >>= 1) v += __shfl_down_sync(0xffffffffu, v, o);
  }
  return v;
}

__global__ void k_prep0(const float* __restrict__ Wcls, const float* __restrict__ Wbb) {
  int i = blockIdx.x * 256 + threadIdx.x;
  if (i < 3) g_acc[i] = 0.f;
  if (i < 512 * 56) {
    int ic = i / 56, ch = i - ic * 56;
    float v = 0.f;
    if (ch < 18) v = Wcls[ch * 512 + ic];
    else if (ch < 54) v = Wbb[(ch - 18) * 512 + ic];
    g_wh[i] = v;
  }
}

__global__ void k_split_w(const float* __restrict__ Wc) {
  int i = blockIdx.x * 256 + threadIdx.x;
  if (i >= 512 * KK) return;
  int oc = i / KK, k = i - oc * KK;
  int tap = k >> 10, ic = k & 1023;
  float v = Wc[(size_t)oc * KK + ic * 9 + tap];
  __nv_bfloat16 hi = __float2bfloat16(v);
  __nv_bfloat16 lo = __float2bfloat16(v - __bfloat162float(hi));
  g_whi[i] = hi; g_wlo[i] = lo;
}

__global__ void k_nhwc(const float* __restrict__ x) {
  __shared__ float t[32][33];
  int s0 = blockIdx.x * 32, ic0 = blockIdx.y * 32, b = blockIdx.z;
  int tx = threadIdx.x, ty = threadIdx.y;
  #pragma unroll
  for (int i = 0; i < 4; i++)
    t[ty + i * 8][tx] = x[((size_t)b * 1024 + ic0 + ty + i * 8) * HW + s0 + tx];
  __syncthreads();
  #pragma unroll
  for (int i = 0; i < 4; i++) {
    float v = t[tx][ty + i * 8];
    __nv_bfloat16 hi = __float2bfloat16(v);
    __nv_bfloat16 lo = __float2bfloat16(v - __bfloat162float(hi));
    size_t o = ((size_t)b * HW + s0 + ty + i * 8) * 1024 + ic0 + tx;
    g_xhi[o] = hi; g_xlo[o] = lo;
  }
}

// ---------------- HMMA implicit-GEMM: 96x128 tile, 256 thr (8 warps, 48x32/warp) ----------------
__global__ void __launch_bounds__(256, 1) k_hmma(const float* __restrict__ bias) {
  extern __shared__ __align__(1024) char smc[];
  const uint32_t smb = smem_u32(smc);
  const int tid  = threadIdx.x;
  const int lane = tid & 31, wid = tid >> 5;
  const int m0 = blockIdx.x * 96;
  const int n0 = blockIdx.y * 128;
  const int b  = m0 / HW;
  const int s0 = m0 - b * HW;
  const int wm = wid & 1, wn = wid >> 1;   // 2(m) x 4(n) warps, 48x32 per warp

  float acc[3][4][4];
  #pragma unroll
  for (int i = 0; i < 3; i++)
    #pragma unroll
    for (int j = 0; j < 4; j++)
      #pragma unroll
      for (int k = 0; k < 4; k++) acc[i][j][k] = 0.f;

  // loader: 16 chunk-cols x 16 row-groups; A rows rT+16t (t<6), B rows rT+16t (t<8)
  const int cA  = tid & 15;
  const int hl  = cA >> 3;
  const int k16 = cA & 7;
  const int rT  = tid >> 4;
  const __nv_bfloat16* xsrc = hl ? g_xlo : g_xhi;
  const __nv_bfloat16* wsrc = hl ? g_wlo : g_whi;

  int hh[6], ww6[6];
  #pragma unroll
  for (int t = 0; t < 6; t++) {
    int sp = s0 + rT + 16 * t;
    hh[t] = sp / 48; ww6[t] = sp - hh[t] * 48;
  }

  auto issue_chunk = [&](int c) {
    const int st = c % 3;
    const uint32_t stb = smb + st * STGB;
    const int tap = c >> 4;
    const int icb = (c & 15) << 6;
    const int dh = tap / 3 - 1, dw = tap % 3 - 1;
    const int koff = icb + k16 * 8;
    #pragma unroll
    for (int t = 0; t < 6; t++) {
      int row = rT + 16 * t;
      int gh = hh[t] + dh, gw = ww6[t] + dw;
      bool ok = ((unsigned)gh < 64u) & ((unsigned)gw < 48u);
      int spg = ok ? (gh * 48 + gw) : 0;
      const void* src = xsrc + (((size_t)b * HW + spg) << 10) + koff;
      cpa16(stb + row * 256 + ((cA ^ (row & 7)) << 4), src, ok ? 16 : 0);
    }
    #pragma unroll
    for (int t = 0; t < 8; t++) {
      int row = rT + 16 * t;
      const void* src = wsrc + (size_t)(n0 + row) * KK + (c << 6) + k16 * 8;
      cpa16(stb + ASZ + row * 256 + ((cA ^ (row & 7)) << 4), src, 16);
    }
    CPA_COMMIT;
  };

  issue_chunk(0);
  issue_chunk(1);

  // fragment addressing (validated mappings from R5/R6)
  const int rowA  = wm * 48 + (lane & 15);
  const int khalf = lane >> 4;
  const int rowB  = wn * 32 + (lane >> 4) * 8 + (lane & 7);
  const int khB   = (lane >> 3) & 1;

  #pragma unroll 1
  for (int c = 0; c < NCH; ++c) {
    CPA_WAIT1;
    __syncthreads();
    if (c + 2 < NCH) issue_chunk(c + 2);
    else CPA_COMMIT;

    const uint32_t aB = smb + (c % 3) * STGB;
    const uint32_t bB = aB + ASZ;
    #pragma unroll
    for (int s = 0; s < 4; s++) {
      uint32_t ah[3][4], al[3][4], bq[2][4], bql[2][4];
      {
        #pragma unroll
        for (int mt = 0; mt < 3; mt++) {
          int r = rowA + mt * 16;
          int cH = 2 * s + khalf;
          int cL = 8 + cH;
          ldsm4(ah[mt], aB + r * 256 + ((cH ^ (r & 7)) << 4));
          ldsm4(al[mt], aB + r * 256 + ((cL ^ (r & 7)) << 4));
        }
        #pragma unroll
        for (int ntp = 0; ntp < 2; ntp++) {
          int r = rowB + ntp * 16;
          int cH = 2 * s + khB;
          int cL = 8 + cH;
          ldsm4(bq[ntp],  bB + r * 256 + ((cH ^ (r & 7)) << 4));
          ldsm4(bql[ntp], bB + r * 256 + ((cL ^ (r & 7)) << 4));
        }
      }
      #pragma unroll
      for (int mt = 0; mt < 3; mt++)
        #pragma unroll
        for (int nt = 0; nt < 4; nt++) {
          const uint32_t* bhF = &bq[nt >> 1][(nt & 1) * 2];
          const uint32_t* blF = &bql[nt >> 1][(nt & 1) * 2];
          mma16816(acc[mt][nt], ah[mt], bhF);
          mma16816(acc[mt][nt], al[mt], bhF);
          mma16816(acc[mt][nt], ah[mt], blF);
        }
    }
  }
  __syncthreads();

  // -------- epilogue: smem transpose [128 oc][96 m] -> coalesced stores, bias+relu --------
  float* so = (float*)smc;   // 48KB
  const int g = lane >> 2, tg = lane & 3;
  #pragma unroll
  for (int mt = 0; mt < 3; mt++)
    #pragma unroll
    for (int nt = 0; nt < 4; nt++) {
      int r0 = wm * 48 + mt * 16 + g;
      int c0 = wn * 32 + nt * 8 + tg * 2;
      so[c0 * 96 + r0]          = acc[mt][nt][0];
      so[(c0 + 1) * 96 + r0]    = acc[mt][nt][1];
      so[c0 * 96 + r0 + 8]      = acc[mt][nt][2];
      so[(c0 + 1) * 96 + r0 + 8]= acc[mt][nt][3];
    }
  __syncthreads();
  #pragma unroll 1
  for (int i = tid; i < 128 * 24; i += 256) {
    int oc = i / 24, mq = i - oc * 24;
    float4 v = ((const float4*)(so + oc * 96))[mq];
    float bz = bias[n0 + oc];
    v.x = fmaxf(v.x + bz, 0.f); v.y = fmaxf(v.y + bz, 0.f);
    v.z = fmaxf(v.z + bz, 0.f); v.w = fmaxf(v.w + bz, 0.f);
    *(float4*)(g_conv1 + ((size_t)(b * 512 + n0 + oc)) * HW + s0 + mq * 4) = v;
  }
}

// ---------------- heads / losses ----------------
__global__ void __launch_bounds__(256) k_heads(const float* __restrict__ bcls,
                                               const float* __restrict__ bbb,
                                               float* __restrict__ out) {
  __shared__ __align__(16) float sx[64 * 128];
  __shared__ __align__(16) float sw[64 * 56];
  const int t = blockIdx.x;
  const int b = t / 24;
  const int sp0 = (t % 24) * 128;
  const int tid = threadIdx.x;
  const int sp = tid & 127;
  const int half = tid >> 7;

  float accv[28];
  #pragma unroll
  for (int j = 0; j < 28; j++) accv[j] = 0.f;

  #pragma unroll 1
  for (int ic0 = 0; ic0 < 512; ic0 += 64) {
    __syncthreads();
    {
      float4* dst = (float4*)sx;
      #pragma unroll 1
      for (int i = tid; i < 2048; i += 256) {
        int ic = i >> 5, c = i & 31;
        dst[i] = *(const float4*)(g_conv1 + (size_t)(b * 512 + ic0 + ic) * HW + sp0 + c * 4);
      }
      float4* dw = (float4*)sw;
      const float4* srw = (const float4*)(g_wh + ic0 * 56);
      #pragma unroll 1
      for (int i = tid; i < 896; i += 256) dw[i] = srw[i];
    }
    __syncthreads();
    #pragma unroll 1
    for (int ic = 0; ic < 64; ic++) {
      float xv = sx[ic * 128 + sp];
      const float* wr = sw + ic * 56 + half * 28;
      #pragma unroll
      for (int j = 0; j < 28; j++) accv[j] = fmaf(xv, wr[j], accv[j]);
    }
  }
  const int chb = half * 28;
  #pragma unroll
  for (int j = 0; j < 28; j++) {
    int ch = chb + j;
    if (ch < 54) {
      float bz = (ch < 18) ? bcls[ch] : bbb[ch - 18];
      float v = accv[j] + bz;
      if (ch < 18) g_cls[(size_t)(b * 18 + ch) * HW + sp0 + sp] = v;
      else         out[SZ_PROB + (size_t)(b * 36 + (ch - 18)) * HW + sp0 + sp] = v;
    }
  }
}

__global__ void __launch_bounds__(256) k_cls(const int* __restrict__ label,
                                             float* __restrict__ out) {
  int idx = blockIdx.x * 256 + threadIdx.x;
  float nll = 0.f, cnt = 0.f;
  if (idx < BB * 9 * HW) {
    int b = idx / (9 * HW);
    int rem = idx - b * (9 * HW);
    int a = rem / HW;
    int s = rem - a * HW;
    float l0 = g_cls[(size_t)(b * 18 + a) * HW + s];
    float l1 = g_cls[(size_t)(b * 18 + a + 9) * HW + s];
    float mx = fmaxf(l0, l1);
    float e0 = expf(l0 - mx), e1 = expf(l1 - mx);
    float sum = e0 + e1, inv = 1.f / sum;
    out[(size_t)(b * 18 + a) * HW + s] = e0 * inv;
    out[(size_t)(b * 18 + a + 9) * HW + s] = e1 * inv;
    int lb = label[idx];
    if (lb >= 0) {
      float chosen = lb ? l1 : l0;
      nll = -(chosen - mx - logf(sum));
      cnt = 1.f;
    }
  }
  float s1 = blockReduceSum(nll);
  if (threadIdx.x == 0) atomicAdd(&g_acc[0], s1);
  float s2 = blockReduceSum(cnt);
  if (threadIdx.x == 0) atomicAdd(&g_acc[1], s2);
}

__global__ void __launch_bounds__(256) k_box(const float* __restrict__ tgt,
                                             const float* __restrict__ iw,
                                             const float* __restrict__ ow,
                                             const float* __restrict__ bbox) {
  int i = blockIdx.x * 256 + threadIdx.x;
  float v = 0.f;
  if (i < SZ_BBOX) {
    float d = iw[i] * (bbox[i] - tgt[i]);
    float ad = fabsf(d);
    float l = (ad < (1.f / 9.f)) ? d * d * 4.5f : (ad - (1.f / 18.f));
    v = ow[i] * l;
  }
  float s = blockReduceSum(v);
  if (threadIdx.x == 0) atomicAdd(&g_acc[2], s);
}

__global__ void k_fin(float* out) {
  out[OUT_LCLS] = g_acc[0] / fmaxf(g_acc[1], 1.f);
  out[OUT_LBOX] = g_acc[2] * 0.125f;
}

// ---------------- host ----------------
extern "C" void kernel_launch(void* const* d_in, const int* in_sizes, int n_in,
                              void* d_out, int out_size) {
  const float* base_feat = (const float*)d_in[0];
  const float* W_conv = (const float*)d_in[1];
  const float* b_conv = (const float*)d_in[2];
  const float* W_cls  = (const float*)d_in[3];
  const float* b_cls  = (const float*)d_in[4];
  const float* W_bbox = (const float*)d_in[5];
  const float* b_bbox = (const float*)d_in[6];
  const int* rpn_label = (const int*)d_in[7];
  const float* tgt = (const float*)d_in[8];
  const float* iw  = (const float*)d_in[9];
  const float* ow  = (const float*)d_in[10];
  float* out = (float*)d_out;

  static int init = 0;
  if (!init) {
    cudaFuncSetAttribute(k_hmma, cudaFuncAttributeMaxDynamicSharedMemorySize, SMEM_HMMA);
    init = 1;
  }

  k_prep0<<<(512 * 56 + 255) / 256, 256>>>(W_cls, W_bbox);
  k_split_w<<<(512 * KK + 255) / 256, 256>>>(W_conv);
  k_nhwc<<<dim3(96, 32, 8), dim3(32, 8)>>>(base_feat);
  k_hmma<<<dim3(256, 4), 256, SMEM_HMMA>>>(b_conv);
  k_heads<<<192, 256>>>(b_cls, b_bbox, out);
  k_cls<<<(BB * 9 * HW + 255) / 256, 256>>>(rpn_label, out);
  k_box<<<(SZ_BBOX + 255) / 256, 256>>>(tgt, iw, ow, out + SZ_PROB);
  k_fin<<<1, 1>>>(out);
}

// round 8
// speedup vs baseline: 1.2392x; 1.1234x over previous
#include <cuda_runtime.h>
#include <cuda_bf16.h>
#include <cstdint>

#define BB 8
#define HW 3072
#define KK 9216
#define SZ_PROB (8*18*3072)
#define SZ_BBOX (8*36*3072)
#define OUT_LCLS (SZ_PROB+SZ_BBOX)
#define OUT_LBOX (SZ_PROB+SZ_BBOX+1)
#define NCH 144
#define ASZ 24576              // A tile bytes: 96 rows * 256B
#define STGB 57344             // ASZ + 128*256
#define SMEM_HMMA (2*STGB)     // 114688 -> 2 CTAs/SM

// ---------------- device scratch ----------------
__device__ float g_conv1[(size_t)BB*512*HW];
__device__ __align__(256) __nv_bfloat16 g_xhi[(size_t)BB*HW*1024];
__device__ __align__(256) __nv_bfloat16 g_xlo[(size_t)BB*HW*1024];
__device__ __align__(256) __nv_bfloat16 g_whi[(size_t)512*KK];
__device__ __align__(256) __nv_bfloat16 g_wlo[(size_t)512*KK];
__device__ float g_wh[512*56];
__device__ float g_cls[SZ_PROB];
__device__ float g_acc[3];

// ---------------- PTX helpers ----------------
__device__ __forceinline__ uint32_t smem_u32(const void* p) {
  uint32_t a;
  asm("{ .reg .u64 t; cvta.to.shared.u64 t, %1; cvt.u32.u64 %0, t; }" : "=r"(a) : "l"(p));
  return a;
}
__device__ __forceinline__ void cpa16(uint32_t dst, const void* src, int sz) {
  asm volatile("cp.async.cg.shared.global [%0], [%1], 16, %2;"
               :: "r"(dst), "l"(src), "r"(sz) : "memory");
}
#define CPA_COMMIT asm volatile("cp.async.commit_group;" ::: "memory")
#define CPA_WAIT1  asm volatile("cp.async.wait_group 1;" ::: "memory")
__device__ __forceinline__ void ldsm4(uint32_t* r, uint32_t a) {
  asm volatile("ldmatrix.sync.aligned.m8n8.x4.shared.b16 {%0,%1,%2,%3}, [%4];"
    : "=r"(r[0]), "=r"(r[1]), "=r"(r[2]), "=r"(r[3]) : "r"(a));
}
__device__ __forceinline__ void mma16816(float* c, const uint32_t* a, const uint32_t* b) {
  asm volatile("mma.sync.aligned.m16n8k16.row.col.f32.bf16.bf16.f32 "
    "{%0,%1,%2,%3}, {%4,%5,%6,%7}, {%8,%9}, {%0,%1,%2,%3};"
    : "+f"(c[0]), "+f"(c[1]), "+f"(c[2]), "+f"(c[3])
    : "r"(a[0]), "r"(a[1]), "r"(a[2]), "r"(a[3]), "r"(b[0]), "r"(b[1]));
}

// ---------------- misc ----------------
__device__ __forceinline__ float blockReduceSum(float v) {
  __shared__ float sh[32];
  __syncthreads();
  #pragma unroll
  for (int o = 16; o; o >>= 1) v += __shfl_down_sync(0xffffffffu, v, o);
  int lane = threadIdx.x & 31, wid = threadIdx.x >> 5;
  if (lane == 0) sh[wid] = v;
  __syncthreads();
  int nw = blockDim.x >> 5;
  v = (threadIdx.x < (unsigned)nw) ? sh[threadIdx.x] : 0.f;
  if (wid == 0) {
    #pragma unroll
    for (int o = 16; o; o >>= 1) v += __shfl_down_sync(0xffffffffu, v, o);
  }
  return v;
}

__global__ void k_prep0(const float* __restrict__ Wcls, const float* __restrict__ Wbb) {
  int i = blockIdx.x * 256 + threadIdx.x;
  if (i < 3) g_acc[i] = 0.f;
  if (i < 512 * 56) {
    int ic = i / 56, ch = i - ic * 56;
    float v = 0.f;
    if (ch < 18) v = Wcls[ch * 512 + ic];
    else if (ch < 54) v = Wbb[(ch - 18) * 512 + ic];
    g_wh[i] = v;
  }
}

__global__ void k_split_w(const float* __restrict__ Wc) {
  int i = blockIdx.x * 256 + threadIdx.x;
  if (i >= 512 * KK) return;
  int oc = i / KK, k = i - oc * KK;
  int tap = k >> 10, ic = k & 1023;
  float v = Wc[(size_t)oc * KK + ic * 9 + tap];
  __nv_bfloat16 hi = __float2bfloat16(v);
  __nv_bfloat16 lo = __float2bfloat16(v - __bfloat162float(hi));
  g_whi[i] = hi; g_wlo[i] = lo;
}

__global__ void k_nhwc(const float* __restrict__ x) {
  __shared__ float t[32][33];
  int s0 = blockIdx.x * 32, ic0 = blockIdx.y * 32, b = blockIdx.z;
  int tx = threadIdx.x, ty = threadIdx.y;
  #pragma unroll
  for (int i = 0; i < 4; i++)
    t[ty + i * 8][tx] = x[((size_t)b * 1024 + ic0 + ty + i * 8) * HW + s0 + tx];
  __syncthreads();
  #pragma unroll
  for (int i = 0; i < 4; i++) {
    float v = t[tx][ty + i * 8];
    __nv_bfloat16 hi = __float2bfloat16(v);
    __nv_bfloat16 lo = __float2bfloat16(v - __bfloat162float(hi));
    size_t o = ((size_t)b * HW + s0 + ty + i * 8) * 1024 + ic0 + tx;
    g_xhi[o] = hi; g_xlo[o] = lo;
  }
}

// ---------------- HMMA implicit-GEMM: 96x128 tile, 2-stage, 2 CTAs/SM ----------------
__global__ void __launch_bounds__(256, 2) k_hmma(const float* __restrict__ bias) {
  extern __shared__ __align__(1024) char smc[];
  const uint32_t smb = smem_u32(smc);
  const int tid  = threadIdx.x;
  const int lane = tid & 31, wid = tid >> 5;
  const int m0 = blockIdx.x * 96;
  const int n0 = blockIdx.y * 128;
  const int b  = m0 / HW;
  const int s0 = m0 - b * HW;
  const int wm = wid & 1, wn = wid >> 1;   // 2(m) x 4(n) warps, 48x32 per warp

  float acc[3][4][4];
  #pragma unroll
  for (int i = 0; i < 3; i++)
    #pragma unroll
    for (int j = 0; j < 4; j++)
      #pragma unroll
      for (int k = 0; k < 4; k++) acc[i][j][k] = 0.f;

  // loader: 16 chunk-cols x 16 row-groups; A rows rT+16t (t<6), B rows rT+16t (t<8)
  const int cA  = tid & 15;
  const int hl  = cA >> 3;
  const int k16 = cA & 7;
  const int rT  = tid >> 4;
  const __nv_bfloat16* xsrc = hl ? g_xlo : g_xhi;
  const __nv_bfloat16* wsrc = hl ? g_wlo : g_whi;

  int hh[6], ww6[6];
  #pragma unroll
  for (int t = 0; t < 6; t++) {
    int sp = s0 + rT + 16 * t;
    hh[t] = sp / 48; ww6[t] = sp - hh[t] * 48;
  }

  auto issue_chunk = [&](int c) {
    const uint32_t stb = smb + (c & 1) * STGB;
    const int tap = c >> 4;
    const int icb = (c & 15) << 6;
    const int dh = tap / 3 - 1, dw = tap % 3 - 1;
    const int koff = icb + k16 * 8;
    #pragma unroll
    for (int t = 0; t < 6; t++) {
      int row = rT + 16 * t;
      int gh = hh[t] + dh, gw = ww6[t] + dw;
      bool ok = ((unsigned)gh < 64u) & ((unsigned)gw < 48u);
      int spg = ok ? (gh * 48 + gw) : 0;
      const void* src = xsrc + (((size_t)b * HW + spg) << 10) + koff;
      cpa16(stb + row * 256 + ((cA ^ (row & 7)) << 4), src, ok ? 16 : 0);
    }
    #pragma unroll
    for (int t = 0; t < 8; t++) {
      int row = rT + 16 * t;
      const void* src = wsrc + (size_t)(n0 + row) * KK + (c << 6) + k16 * 8;
      cpa16(stb + ASZ + row * 256 + ((cA ^ (row & 7)) << 4), src, 16);
    }
    CPA_COMMIT;
  };

  issue_chunk(0);

  // fragment addressing (validated mappings)
  const int rowA  = wm * 48 + (lane & 15);
  const int khalf = lane >> 4;
  const int rowB  = wn * 32 + (lane >> 4) * 8 + (lane & 7);
  const int khB   = (lane >> 3) & 1;

  #pragma unroll 1
  for (int c = 0; c < NCH; ++c) {
    if (c + 1 < NCH) issue_chunk(c + 1);
    else CPA_COMMIT;
    CPA_WAIT1;
    __syncthreads();

    const uint32_t aB = smb + (c & 1) * STGB;
    const uint32_t bB = aB + ASZ;
    #pragma unroll
    for (int s = 0; s < 4; s++) {
      uint32_t ah[3][4], al[3][4], bq[2][4], bql[2][4];
      {
        #pragma unroll
        for (int mt = 0; mt < 3; mt++) {
          int r = rowA + mt * 16;
          int cH = 2 * s + khalf;
          int cL = 8 + cH;
          ldsm4(ah[mt], aB + r * 256 + ((cH ^ (r & 7)) << 4));
          ldsm4(al[mt], aB + r * 256 + ((cL ^ (r & 7)) << 4));
        }
        #pragma unroll
        for (int ntp = 0; ntp < 2; ntp++) {
          int r = rowB + ntp * 16;
          int cH = 2 * s + khB;
          int cL = 8 + cH;
          ldsm4(bq[ntp],  bB + r * 256 + ((cH ^ (r & 7)) << 4));
          ldsm4(bql[ntp], bB + r * 256 + ((cL ^ (r & 7)) << 4));
        }
      }
      #pragma unroll
      for (int mt = 0; mt < 3; mt++)
        #pragma unroll
        for (int nt = 0; nt < 4; nt++) {
          const uint32_t* bhF = &bq[nt >> 1][(nt & 1) * 2];
          const uint32_t* blF = &bql[nt >> 1][(nt & 1) * 2];
          mma16816(acc[mt][nt], ah[mt], bhF);
          mma16816(acc[mt][nt], al[mt], bhF);
          mma16816(acc[mt][nt], ah[mt], blF);
        }
    }
    __syncthreads();
  }

  // -------- epilogue: smem transpose [128 oc][96 m] -> coalesced stores, bias+relu --------
  float* so = (float*)smc;   // 48KB
  const int g = lane >> 2, tg = lane & 3;
  #pragma unroll
  for (int mt = 0; mt < 3; mt++)
    #pragma unroll
    for (int nt = 0; nt < 4; nt++) {
      int r0 = wm * 48 + mt * 16 + g;
      int c0 = wn * 32 + nt * 8 + tg * 2;
      so[c0 * 96 + r0]          = acc[mt][nt][0];
      so[(c0 + 1) * 96 + r0]    = acc[mt][nt][1];
      so[c0 * 96 + r0 + 8]      = acc[mt][nt][2];
      so[(c0 + 1) * 96 + r0 + 8]= acc[mt][nt][3];
    }
  __syncthreads();
  #pragma unroll 1
  for (int i = tid; i < 128 * 24; i += 256) {
    int oc = i / 24, mq = i - oc * 24;
    float4 v = ((const float4*)(so + oc * 96))[mq];
    float bz = bias[n0 + oc];
    v.x = fmaxf(v.x + bz, 0.f); v.y = fmaxf(v.y + bz, 0.f);
    v.z = fmaxf(v.z + bz, 0.f); v.w = fmaxf(v.w + bz, 0.f);
    *(float4*)(g_conv1 + ((size_t)(b * 512 + n0 + oc)) * HW + s0 + mq * 4) = v;
  }
}

// ---------------- heads / losses ----------------
__global__ void __launch_bounds__(256) k_heads(const float* __restrict__ bcls,
                                               const float* __restrict__ bbb,
                                               float* __restrict__ out) {
  __shared__ __align__(16) float sx[64 * 128];
  __shared__ __align__(16) float sw[64 * 56];
  const int t = blockIdx.x;
  const int b = t / 24;
  const int sp0 = (t % 24) * 128;
  const int tid = threadIdx.x;
  const int sp = tid & 127;
  const int half = tid >> 7;

  float accv[28];
  #pragma unroll
  for (int j = 0; j < 28; j++) accv[j] = 0.f;

  #pragma unroll 1
  for (int ic0 = 0; ic0 < 512; ic0 += 64) {
    __syncthreads();
    {
      float4* dst = (float4*)sx;
      #pragma unroll 1
      for (int i = tid; i < 2048; i += 256) {
        int ic = i >> 5, c = i & 31;
        dst[i] = *(const float4*)(g_conv1 + (size_t)(b * 512 + ic0 + ic) * HW + sp0 + c * 4);
      }
      float4* dw = (float4*)sw;
      const float4* srw = (const float4*)(g_wh + ic0 * 56);
      #pragma unroll 1
      for (int i = tid; i < 896; i += 256) dw[i] = srw[i];
    }
    __syncthreads();
    #pragma unroll 1
    for (int ic = 0; ic < 64; ic++) {
      float xv = sx[ic * 128 + sp];
      const float* wr = sw + ic * 56 + half * 28;
      #pragma unroll
      for (int j = 0; j < 28; j++) accv[j] = fmaf(xv, wr[j], accv[j]);
    }
  }
  const int chb = half * 28;
  #pragma unroll
  for (int j = 0; j < 28; j++) {
    int ch = chb + j;
    if (ch < 54) {
      float bz = (ch < 18) ? bcls[ch] : bbb[ch - 18];
      float v = accv[j] + bz;
      if (ch < 18) g_cls[(size_t)(b * 18 + ch) * HW + sp0 + sp] = v;
      else         out[SZ_PROB + (size_t)(b * 36 + (ch - 18)) * HW + sp0 + sp] = v;
    }
  }
}

__global__ void __launch_bounds__(256) k_cls(const int* __restrict__ label,
                                             float* __restrict__ out) {
  int idx = blockIdx.x * 256 + threadIdx.x;
  float nll = 0.f, cnt = 0.f;
  if (idx < BB * 9 * HW) {
    int b = idx / (9 * HW);
    int rem = idx - b * (9 * HW);
    int a = rem / HW;
    int s = rem - a * HW;
    float l0 = g_cls[(size_t)(b * 18 + a) * HW + s];
    float l1 = g_cls[(size_t)(b * 18 + a + 9) * HW + s];
    float mx = fmaxf(l0, l1);
    float e0 = expf(l0 - mx), e1 = expf(l1 - mx);
    float sum = e0 + e1, inv = 1.f / sum;
    out[(size_t)(b * 18 + a) * HW + s] = e0 * inv;
    out[(size_t)(b * 18 + a + 9) * HW + s] = e1 * inv;
    int lb = label[idx];
    if (lb >= 0) {
      float chosen = lb ? l1 : l0;
      nll = -(chosen - mx - logf(sum));
      cnt = 1.f;
    }
  }
  float s1 = blockReduceSum(nll);
  if (threadIdx.x == 0) atomicAdd(&g_acc[0], s1);
  float s2 = blockReduceSum(cnt);
  if (threadIdx.x == 0) atomicAdd(&g_acc[1], s2);
}

__global__ void __launch_bounds__(256) k_box(const float* __restrict__ tgt,
                                             const float* __restrict__ iw,
                                             const float* __restrict__ ow,
                                             const float* __restrict__ bbox) {
  int i = blockIdx.x * 256 + threadIdx.x;
  float v = 0.f;
  if (i < SZ_BBOX) {
    float d = iw[i] * (bbox[i] - tgt[i]);
    float ad = fabsf(d);
    float l = (ad < (1.f / 9.f)) ? d * d * 4.5f : (ad - (1.f / 18.f));
    v = ow[i] * l;
  }
  float s = blockReduceSum(v);
  if (threadIdx.x == 0) atomicAdd(&g_acc[2], s);
}

__global__ void k_fin(float* out) {
  out[OUT_LCLS] = g_acc[0] / fmaxf(g_acc[1], 1.f);
  out[OUT_LBOX] = g_acc[2] * 0.125f;
}

// ---------------- host ----------------
extern "C" void kernel_launch(void* const* d_in, const int* in_sizes, int n_in,
                              void* d_out, int out_size) {
  const float* base_feat = (const float*)d_in[0];
  const float* W_conv = (const float*)d_in[1];
  const float* b_conv = (const float*)d_in[2];
  const float* W_cls  = (const float*)d_in[3];
  const float* b_cls  = (const float*)d_in[4];
  const float* W_bbox = (const float*)d_in[5];
  const float* b_bbox = (const float*)d_in[6];
  const int* rpn_label = (const int*)d_in[7];
  const float* tgt = (const float*)d_in[8];
  const float* iw  = (const float*)d_in[9];
  const float* ow  = (const float*)d_in[10];
  float* out = (float*)d_out;

  static int init = 0;
  if (!init) {
    cudaFuncSetAttribute(k_hmma, cudaFuncAttributeMaxDynamicSharedMemorySize, SMEM_HMMA);
    init = 1;
  }

  k_prep0<<<(512 * 56 + 255) / 256, 256>>>(W_cls, W_bbox);
  k_split_w<<<(512 * KK + 255) / 256, 256>>>(W_conv);
  k_nhwc<<<dim3(96, 32, 8), dim3(32, 8)>>>(base_feat);
  k_hmma<<<dim3(256, 4), 256, SMEM_HMMA>>>(b_conv);
  k_heads<<<192, 256>>>(b_cls, b_bbox, out);
  k_cls<<<(BB * 9 * HW + 255) / 256, 256>>>(rpn_label, out);
  k_box<<<(SZ_BBOX + 255) / 256, 256>>>(tgt, iw, ow, out + SZ_PROB);
  k_fin<<<1, 1>>>(out);
}